// round 1
// baseline (speedup 1.0000x reference)
#include <cuda_runtime.h>
#include <math.h>

// ---------------- problem constants (fixed shapes for this dataset) --------
#define T_LEN   64000
#define B_SZ    2
#define NS      3999            // (T - 32)/16 + 1
#define NF      3999
#define BS_TOT  (B_SZ * NS)     // 7998
#define GHID    64
#define HFAST   32
#define ROWS    16              // sequences per CTA (slow kernel)
#define NCTA_SLOW ((BS_TOT + ROWS - 1) / ROWS)   // 500

// smem layout (floats): seq[32][64][16] | Wih[64][192] | Whh[64][192] | scratch[512]
#define SEQ_F   (32 * 64 * 16)  // 32768
#define W_F     (64 * 192)      // 12288
#define SMEM_FLOATS (SEQ_F + 2 * W_F + 512)       // 57856
#define SMEM_BYTES  (SMEM_FLOATS * 4)             // 231424

// ---------------- device scratch (static, allocation-free) -----------------
__device__ float d_A[BS_TOT * HFAST];
__device__ float d_G[BS_TOT * HFAST];
__device__ float d_S[BS_TOT * 32];   // s_hat [B*NF][32]

// ---------------- helpers ---------------------------------------------------
__device__ __forceinline__ float sigmoidf_(float x) {
    return __fdividef(1.0f, 1.0f + __expf(-x));
}
__device__ __forceinline__ float tanhf_(float x) {
    float e = __expf(-2.0f * fabsf(x));
    float t = __fdividef(1.0f - e, 1.0f + e);
    return copysignf(t, x);
}
__device__ __forceinline__ float gatefn(float ar, float az, float axn, float ahn, float hp) {
    float r = sigmoidf_(ar);
    float z = sigmoidf_(az);
    float n = tanhf_(axn + r * ahn);
    return z * (hp - n) + n;
}

// ---------------- slow path: 4-layer GRU stack + head ----------------------
__global__ void __launch_bounds__(256, 1) slow_kernel(
    const float* __restrict__ x,
    const float* __restrict__ siW,  const float* __restrict__ sib,
    const float* __restrict__ Wih,  const float* __restrict__ Whh,
    const float* __restrict__ bih,  const float* __restrict__ bhh,
    const float* __restrict__ soW,  const float* __restrict__ sob,
    const float* __restrict__ s2sW, const float* __restrict__ s2sb)
{
    extern __shared__ float sm[];
    float* seq  = sm;                 // [t][k][row]  pre-relu activations
    float* Wihs = sm + SEQ_F;         // [k][192]
    float* Whhs = Wihs + W_F;         // [k][192]
    float* scr  = Whhs + W_F;         // 512 floats

    const int tid = threadIdx.x;
    const int u   = tid & 63;         // hidden unit / output col
    const int rb  = tid >> 6;         // row block 0..3
    const int r0  = rb * 4;
    const int g0  = blockIdx.x * ROWS;

    // ---- load x windows into scratch: xw[r][t] -----------------------------
    for (int i = tid; i < ROWS * 32; i += 256) {
        int r = i >> 5, t = i & 31;
        int g = g0 + r;
        float v = 0.0f;
        if (g < BS_TOT) {
            int b = g / NS;
            int s = g - b * NS;
            v = x[b * T_LEN + s * 16 + t];
        }
        scr[i] = v;
    }
    __syncthreads();

    // ---- layer-0 input (pre-relu affine) into seq --------------------------
    for (int i = tid; i < SEQ_F; i += 256) {
        int r = i & 15;
        int k = (i >> 4) & 63;
        int t = i >> 10;
        seq[i] = scr[r * 32 + t] * __ldg(&siW[k]) + __ldg(&sib[k]);
    }
    __syncthreads();

    // ---- 4 GRU layers -------------------------------------------------------
    for (int l = 0; l < 4; ++l) {
        const float* gW = Wih + l * W_F;
        const float* gU = Whh + l * W_F;
        for (int i = tid * 4; i < W_F; i += 256 * 4) {
            *(float4*)&Wihs[i] = *(const float4*)&gW[i];
            *(float4*)&Whhs[i] = *(const float4*)&gU[i];
        }
        const float b_r  = __ldg(&bih[l*192 + u])       + __ldg(&bhh[l*192 + u]);
        const float b_z  = __ldg(&bih[l*192 + 64 + u])  + __ldg(&bhh[l*192 + 64 + u]);
        const float b_xn = __ldg(&bih[l*192 + 128 + u]);
        const float b_hn = __ldg(&bhh[l*192 + 128 + u]);
        __syncthreads();

        for (int t = 0; t < 32; ++t) {
            float ar[4], az[4], an[4], ah[4];
            #pragma unroll
            for (int i = 0; i < 4; ++i) { ar[i]=b_r; az[i]=b_z; an[i]=b_xn; ah[i]=b_hn; }

            // input GEMM: relu(prev-layer h_t) @ Wih
            const float* st = seq + t * 1024;
            #pragma unroll 8
            for (int k = 0; k < 64; ++k) {
                float4 v = *(const float4*)(st + k * 16 + r0);
                v.x = fmaxf(v.x, 0.f); v.y = fmaxf(v.y, 0.f);
                v.z = fmaxf(v.z, 0.f); v.w = fmaxf(v.w, 0.f);
                float wr = Wihs[k*192 + u];
                float wz = Wihs[k*192 + 64 + u];
                float wn = Wihs[k*192 + 128 + u];
                ar[0]+=v.x*wr; ar[1]+=v.y*wr; ar[2]+=v.z*wr; ar[3]+=v.w*wr;
                az[0]+=v.x*wz; az[1]+=v.y*wz; az[2]+=v.z*wz; az[3]+=v.w*wz;
                an[0]+=v.x*wn; an[1]+=v.y*wn; an[2]+=v.z*wn; an[3]+=v.w*wn;
            }

            float4 hp = make_float4(0.f, 0.f, 0.f, 0.f);
            if (t > 0) {
                // recurrent GEMM: h_{t-1} (pre-relu) @ Whh
                const float* sp = seq + (t - 1) * 1024;
                #pragma unroll 8
                for (int k = 0; k < 64; ++k) {
                    float4 v = *(const float4*)(sp + k * 16 + r0);
                    float wr = Whhs[k*192 + u];
                    float wz = Whhs[k*192 + 64 + u];
                    float wn = Whhs[k*192 + 128 + u];
                    ar[0]+=v.x*wr; ar[1]+=v.y*wr; ar[2]+=v.z*wr; ar[3]+=v.w*wr;
                    az[0]+=v.x*wz; az[1]+=v.y*wz; az[2]+=v.z*wz; az[3]+=v.w*wz;
                    ah[0]+=v.x*wn; ah[1]+=v.y*wn; ah[2]+=v.z*wn; ah[3]+=v.w*wn;
                }
                hp = *(const float4*)(sp + u * 16 + r0);
            }
            __syncthreads();   // all reads of seq[t] done -> safe to overwrite

            float4 hn;
            hn.x = gatefn(ar[0], az[0], an[0], ah[0], hp.x);
            hn.y = gatefn(ar[1], az[1], an[1], ah[1], hp.y);
            hn.z = gatefn(ar[2], az[2], an[2], ah[2], hp.z);
            hn.w = gatefn(ar[3], az[3], an[3], ah[3], hp.w);
            *(float4*)(seq + t * 1024 + u * 16 + r0) = hn;
            __syncthreads();   // writes visible before next step's reads
        }
    }

    // ---- head: slow_feat = relu(h_last) @ soW + sob; eps = sf @ s2sW + s2sb
    for (int i = tid * 4; i < 64 * 64; i += 256 * 4) {
        *(float4*)&Wihs[i] = *(const float4*)&soW[i];
        *(float4*)&Whhs[i] = *(const float4*)&s2sW[i];
    }
    __syncthreads();

    {
        float acc[4];
        float bb = __ldg(&sob[u]);
        #pragma unroll
        for (int i = 0; i < 4; ++i) acc[i] = bb;
        const float* sl = seq + 31 * 1024;
        #pragma unroll 8
        for (int k = 0; k < 64; ++k) {
            float4 v = *(const float4*)(sl + k * 16 + r0);
            v.x = fmaxf(v.x, 0.f); v.y = fmaxf(v.y, 0.f);
            v.z = fmaxf(v.z, 0.f); v.w = fmaxf(v.w, 0.f);
            float w = Wihs[k * 64 + u];
            acc[0]+=v.x*w; acc[1]+=v.y*w; acc[2]+=v.z*w; acc[3]+=v.w*w;
        }
        // store slow_feat (no activation) into seq[0] region: [c][row]
        *(float4*)(seq + u * 16 + r0) = make_float4(acc[0], acc[1], acc[2], acc[3]);
    }
    __syncthreads();

    {
        float acc[4];
        float bb = __ldg(&s2sb[u]);
        #pragma unroll
        for (int i = 0; i < 4; ++i) acc[i] = bb;
        #pragma unroll 8
        for (int k = 0; k < 64; ++k) {
            float4 v = *(const float4*)(seq + k * 16 + r0);
            float w = Whhs[k * 64 + u];
            acc[0]+=v.x*w; acc[1]+=v.y*w; acc[2]+=v.z*w; acc[3]+=v.w*w;
        }
        #pragma unroll
        for (int i = 0; i < 4; ++i) {
            int g = g0 + r0 + i;
            if (g < BS_TOT) {
                if (u < HFAST) d_A[g * HFAST + u] = sigmoidf_(acc[i]);
                else           d_G[g * HFAST + (u - HFAST)] = acc[i];
            }
        }
    }
}

// ---------------- fast path: diagonal SSM, warp per frame ------------------
__global__ void __launch_bounds__(256) fast_kernel(
    const float* __restrict__ x,
    const float* __restrict__ finW, const float* __restrict__ finb,
    const float* __restrict__ foutW, const float* __restrict__ foutb)
{
    int w = (blockIdx.x * blockDim.x + threadIdx.x) >> 5;   // frame index
    int h = threadIdx.x & 31;                               // channel
    if (w >= BS_TOT) return;
    int b = w / NF;
    int f = w - b * NF;

    float A  = d_A[w * HFAST + h];
    float G  = d_G[w * HFAST + h];
    float fw = __ldg(&finW[h]);
    float fb = __ldg(&finb[h]);
    float fo = __ldg(&foutW[h]);
    float fob = __ldg(&foutb[0]);

    const float* xp = x + b * T_LEN + f * 16;
    float hs = 0.f;
    #pragma unroll
    for (int t = 0; t < 32; ++t) {
        float e = (xp[t] * fw + fb) * G;
        hs = A * hs + e;
        float y = hs * fo;
        #pragma unroll
        for (int m = 16; m; m >>= 1) y += __shfl_xor_sync(0xffffffffu, y, m);
        if (h == t) d_S[w * 32 + t] = y + fob;
    }
}

// ---------------- overlap-add gather (deterministic, no atomics) -----------
__global__ void __launch_bounds__(256) oadd_kernel(float* __restrict__ out)
{
    int idx = blockIdx.x * blockDim.x + threadIdx.x;
    if (idx >= B_SZ * T_LEN) return;
    int b = idx / T_LEN;
    int i = idx - b * T_LEN;
    int f1 = i >> 4;
    int j  = i & 15;
    float v = 0.f;
    if (f1 < NF) v += d_S[(b * NF + f1) * 32 + j];
    if (f1 >= 1) v += d_S[(b * NF + f1 - 1) * 32 + j + 16];
    out[idx] = v;
}

// ---------------- launch -----------------------------------------------------
extern "C" void kernel_launch(void* const* d_in, const int* in_sizes, int n_in,
                              void* d_out, int out_size)
{
    const float* x    = (const float*)d_in[0];
    const float* siW  = (const float*)d_in[1];
    const float* sib  = (const float*)d_in[2];
    const float* Wih  = (const float*)d_in[3];
    const float* Whh  = (const float*)d_in[4];
    const float* bih  = (const float*)d_in[5];
    const float* bhh  = (const float*)d_in[6];
    const float* soW  = (const float*)d_in[7];
    const float* sob  = (const float*)d_in[8];
    const float* s2sW = (const float*)d_in[9];
    const float* s2sb = (const float*)d_in[10];
    const float* finW = (const float*)d_in[11];
    const float* finb = (const float*)d_in[12];
    const float* foW  = (const float*)d_in[13];
    const float* fob  = (const float*)d_in[14];
    float* out = (float*)d_out;

    cudaFuncSetAttribute(slow_kernel,
                         cudaFuncAttributeMaxDynamicSharedMemorySize, SMEM_BYTES);

    slow_kernel<<<NCTA_SLOW, 256, SMEM_BYTES>>>(
        x, siW, sib, Wih, Whh, bih, bhh, soW, sob, s2sW, s2sb);

    int fast_blocks = (BS_TOT * 32 + 255) / 256;   // 1000
    fast_kernel<<<fast_blocks, 256>>>(x, finW, finb, foW, fob);

    int oadd_blocks = (B_SZ * T_LEN + 255) / 256;  // 500
    oadd_kernel<<<oadd_blocks, 256>>>(out);
}

// round 2
// speedup vs baseline: 1.1805x; 1.1805x over previous
#include <cuda_runtime.h>
#include <math.h>

// ---------------- problem constants ----------------------------------------
#define T_LEN   64000
#define B_SZ    2
#define NS      3999
#define NF      3999
#define BS_TOT  (B_SZ * NS)        // 7998
#define HFAST   32
#define ROWS    8                  // sequences per CTA
#define NCTA_SLOW ((BS_TOT + ROWS - 1) / ROWS)   // 1000

// smem layout (floats):
//   seq  [32][64][8]          16384
//   wTih [64][196]            12544   (u-major transposed, [u][gate*64+k])
//   wThh [64][196]            12544
//   scr  [512]                  512   (xw at init, slow_feat at head)
#define SEQ_F   (32 * 64 * 8)
#define WT_STR  196
#define WT_F    (64 * WT_STR)
#define OFF_WIH SEQ_F
#define OFF_WHH (SEQ_F + WT_F)
#define OFF_SCR (SEQ_F + 2 * WT_F)
#define SMEM_FLOATS (OFF_SCR + 512)
#define SMEM_BYTES  (SMEM_FLOATS * 4)            // 167936

// ---------------- device scratch --------------------------------------------
__device__ float d_A[BS_TOT * HFAST];
__device__ float d_G[BS_TOT * HFAST];
__device__ float d_S[BS_TOT * 32];

// ---------------- f32x2 helpers ---------------------------------------------
typedef unsigned long long u64;

__device__ __forceinline__ u64 pack2(float x, float y) {
    u64 r; asm("mov.b64 %0,{%1,%2};" : "=l"(r) : "f"(x), "f"(y)); return r;
}
__device__ __forceinline__ void unpack2(u64 v, float& x, float& y) {
    asm("mov.b64 {%0,%1},%2;" : "=f"(x), "=f"(y) : "l"(v));
}
__device__ __forceinline__ void ffma2(u64& d, u64 a, u64 b) {
    asm("fma.rn.f32x2 %0,%1,%2,%0;" : "+l"(d) : "l"(a), "l"(b));
}

__device__ __forceinline__ float sigmoidf_(float x) {
    return __fdividef(1.0f, 1.0f + __expf(-x));
}
__device__ __forceinline__ float tanhf_(float x) {
    float e = __expf(-2.0f * fabsf(x));
    float t = __fdividef(1.0f - e, 1.0f + e);
    return copysignf(t, x);
}
__device__ __forceinline__ float gatefn(float ar, float az, float an, float ah, float hp) {
    float r = sigmoidf_(ar);
    float z = sigmoidf_(az);
    float n = tanhf_(an + r * ah);
    return z * (hp - n) + n;
}

// ---------------- slow path --------------------------------------------------
__global__ void __launch_bounds__(128, 1) slow_kernel(
    const float* __restrict__ x,
    const float* __restrict__ siW,  const float* __restrict__ sib,
    const float* __restrict__ Wih,  const float* __restrict__ Whh,
    const float* __restrict__ bih,  const float* __restrict__ bhh,
    const float* __restrict__ soW,  const float* __restrict__ sob,
    const float* __restrict__ s2sW, const float* __restrict__ s2sb)
{
    extern __shared__ float sm[];
    float* seq  = sm;              // [t][k][row] : layer I/O + recurrent state
    float* wih  = sm + OFF_WIH;    // [u][g*64+k] transposed, stride 196
    float* whh  = sm + OFF_WHH;
    float* scr  = sm + OFF_SCR;

    const int tid = threadIdx.x;
    const int u   = tid & 63;
    const int rb  = tid >> 6;      // 0..1
    const int r0  = rb * 4;
    const int g0  = blockIdx.x * ROWS;
    const int u196 = u * WT_STR;

    // ---- x windows into scr: xw[r][t] ---------------------------------------
    for (int i = tid; i < ROWS * 32; i += 128) {
        int r = i >> 5, t = i & 31;
        int g = g0 + r;
        float v = 0.0f;
        if (g < BS_TOT) {
            int b = g / NS;
            int s = g - b * NS;
            v = x[b * T_LEN + s * 16 + t];
        }
        scr[i] = v;
    }
    __syncthreads();

    // ---- layer-0 input: seq[t][k][r] = relu(xw*W+b) --------------------------
    for (int i = tid; i < SEQ_F; i += 128) {
        int r = i & 7;
        int k = (i >> 3) & 63;
        int t = i >> 9;
        seq[i] = fmaxf(scr[r * 32 + t] * __ldg(&siW[k]) + __ldg(&sib[k]), 0.0f);
    }

    // ---- 4 GRU layers ---------------------------------------------------------
    for (int l = 0; l < 4; ++l) {
        // load + transpose weights: wT[u][g*64+k] = W[k][g*64+u]
        const float* gW = Wih + l * 12288;
        const float* gU = Whh + l * 12288;
        __syncthreads();
        for (int i = tid; i < 12288; i += 128) {
            int k = i / 192, j = i - k * 192;
            int g = j >> 6, uu = j & 63;
            wih[uu * WT_STR + g * 64 + k] = gW[i];
            whh[uu * WT_STR + g * 64 + k] = gU[i];
        }
        const float b_r  = __ldg(&bih[l*192 + u])       + __ldg(&bhh[l*192 + u]);
        const float b_z  = __ldg(&bih[l*192 + 64 + u])  + __ldg(&bhh[l*192 + 64 + u]);
        const float b_xn = __ldg(&bih[l*192 + 128 + u]);
        const float b_hn = __ldg(&bhh[l*192 + 128 + u]);
        const u64 b2r = pack2(b_r,  b_r);
        const u64 b2z = pack2(b_z,  b_z);
        const u64 b2n = pack2(b_xn, b_xn);
        const u64 b2h = pack2(b_hn, b_hn);
        __syncthreads();

        float hp[4] = {0.f, 0.f, 0.f, 0.f};

        for (int t = 0; t < 32; ++t) {
            u64 ar[2] = {b2r, b2r};
            u64 az[2] = {b2z, b2z};
            u64 an[2] = {b2n, b2n};
            u64 ah[2] = {b2h, b2h};

            // ---- Wih GEMM: reads seq[t] (relu'd prev-layer output) ----------
            {
                const float* st = seq + t * 512 + r0;
                #pragma unroll 4
                for (int k0 = 0; k0 < 64; k0 += 4) {
                    float4 wr = *(const float4*)(wih + u196 + k0);
                    float4 wz = *(const float4*)(wih + u196 + 64 + k0);
                    float4 wn = *(const float4*)(wih + u196 + 128 + k0);
                    const float* wrp = &wr.x;
                    const float* wzp = &wz.x;
                    const float* wnp = &wn.x;
                    #pragma unroll
                    for (int j = 0; j < 4; ++j) {
                        ulonglong2 s = *(const ulonglong2*)(st + (k0 + j) * 8);
                        u64 w2;
                        w2 = pack2(wrp[j], wrp[j]);
                        ffma2(ar[0], s.x, w2); ffma2(ar[1], s.y, w2);
                        w2 = pack2(wzp[j], wzp[j]);
                        ffma2(az[0], s.x, w2); ffma2(az[1], s.y, w2);
                        w2 = pack2(wnp[j], wnp[j]);
                        ffma2(an[0], s.x, w2); ffma2(an[1], s.y, w2);
                    }
                }
            }
            // ---- Whh GEMM: reads seq[t-1] (pre-relu h_{t-1}) -----------------
            if (t > 0) {
                const float* sp = seq + (t - 1) * 512 + r0;
                #pragma unroll 4
                for (int k0 = 0; k0 < 64; k0 += 4) {
                    float4 wr = *(const float4*)(whh + u196 + k0);
                    float4 wz = *(const float4*)(whh + u196 + 64 + k0);
                    float4 wn = *(const float4*)(whh + u196 + 128 + k0);
                    const float* wrp = &wr.x;
                    const float* wzp = &wz.x;
                    const float* wnp = &wn.x;
                    #pragma unroll
                    for (int j = 0; j < 4; ++j) {
                        ulonglong2 s = *(const ulonglong2*)(sp + (k0 + j) * 8);
                        u64 w2;
                        w2 = pack2(wrp[j], wrp[j]);
                        ffma2(ar[0], s.x, w2); ffma2(ar[1], s.y, w2);
                        w2 = pack2(wzp[j], wzp[j]);
                        ffma2(az[0], s.x, w2); ffma2(az[1], s.y, w2);
                        w2 = pack2(wnp[j], wnp[j]);
                        ffma2(ah[0], s.x, w2); ffma2(ah[1], s.y, w2);
                    }
                }
            }
            __syncthreads();   // all reads of seq[t], seq[t-1] complete

            float a0, a1, hn[4];
            float zr[4], zz[4], zn[4], zh[4];
            unpack2(ar[0], zr[0], zr[1]); unpack2(ar[1], zr[2], zr[3]);
            unpack2(az[0], zz[0], zz[1]); unpack2(az[1], zz[2], zz[3]);
            unpack2(an[0], zn[0], zn[1]); unpack2(an[1], zn[2], zn[3]);
            unpack2(ah[0], zh[0], zh[1]); unpack2(ah[1], zh[2], zh[3]);
            (void)a0; (void)a1;
            #pragma unroll
            for (int i = 0; i < 4; ++i)
                hn[i] = gatefn(zr[i], zz[i], zn[i], zh[i], hp[i]);

            // write pre-relu h_t -> seq[t]; relu(h_{t-1}) -> seq[t-1]
            *(float4*)(seq + t * 512 + u * 8 + r0) =
                make_float4(hn[0], hn[1], hn[2], hn[3]);
            if (t > 0) {
                *(float4*)(seq + (t - 1) * 512 + u * 8 + r0) =
                    make_float4(fmaxf(hp[0], 0.f), fmaxf(hp[1], 0.f),
                                fmaxf(hp[2], 0.f), fmaxf(hp[3], 0.f));
            }
            #pragma unroll
            for (int i = 0; i < 4; ++i) hp[i] = hn[i];
            __syncthreads();   // writes visible before next step
        }
        // finalize: relu(h_31) -> seq[31]
        *(float4*)(seq + 31 * 512 + u * 8 + r0) =
            make_float4(fmaxf(hp[0], 0.f), fmaxf(hp[1], 0.f),
                        fmaxf(hp[2], 0.f), fmaxf(hp[3], 0.f));
        __syncthreads();
    }

    // ---- head: slow_feat = seq[31] @ soW + sob ; eps = sf @ s2sW + s2sb ------
    // load soW into wih region (plain [k][64]), s2sW into whh region
    for (int i = tid; i < 64 * 64; i += 128) {
        wih[i] = soW[i];
        whh[i] = s2sW[i];
    }
    __syncthreads();

    {
        float acc[4];
        float bb = __ldg(&sob[u]);
        #pragma unroll
        for (int i = 0; i < 4; ++i) acc[i] = bb;
        const float* sl = seq + 31 * 512 + r0;    // already relu'd
        #pragma unroll 8
        for (int k = 0; k < 64; ++k) {
            float4 v = *(const float4*)(sl + k * 8);
            float w = wih[k * 64 + u];
            acc[0] += v.x * w; acc[1] += v.y * w;
            acc[2] += v.z * w; acc[3] += v.w * w;
        }
        // slow_feat -> scr[k=u][row]
        *(float4*)(scr + u * 8 + r0) = make_float4(acc[0], acc[1], acc[2], acc[3]);
    }
    __syncthreads();

    {
        float acc[4];
        float bb = __ldg(&s2sb[u]);
        #pragma unroll
        for (int i = 0; i < 4; ++i) acc[i] = bb;
        #pragma unroll 8
        for (int k = 0; k < 64; ++k) {
            float4 v = *(const float4*)(scr + k * 8 + r0);
            float w = whh[k * 64 + u];
            acc[0] += v.x * w; acc[1] += v.y * w;
            acc[2] += v.z * w; acc[3] += v.w * w;
        }
        #pragma unroll
        for (int i = 0; i < 4; ++i) {
            int g = g0 + r0 + i;
            if (g < BS_TOT) {
                if (u < HFAST) d_A[g * HFAST + u] = sigmoidf_(acc[i]);
                else           d_G[g * HFAST + (u - HFAST)] = acc[i];
            }
        }
    }
}

// ---------------- fast path: diagonal SSM, warp per frame -------------------
__global__ void __launch_bounds__(256) fast_kernel(
    const float* __restrict__ x,
    const float* __restrict__ finW, const float* __restrict__ finb,
    const float* __restrict__ foutW, const float* __restrict__ foutb)
{
    int w = (blockIdx.x * blockDim.x + threadIdx.x) >> 5;
    int h = threadIdx.x & 31;
    if (w >= BS_TOT) return;
    int b = w / NF;
    int f = w - b * NF;

    float A  = d_A[w * HFAST + h];
    float G  = d_G[w * HFAST + h];
    float fw = __ldg(&finW[h]);
    float fb = __ldg(&finb[h]);
    float fo = __ldg(&foutW[h]);
    float fob = __ldg(&foutb[0]);

    const float* xp = x + b * T_LEN + f * 16;
    float hs = 0.f;
    #pragma unroll
    for (int t = 0; t < 32; ++t) {
        float e = (xp[t] * fw + fb) * G;
        hs = A * hs + e;
        float y = hs * fo;
        #pragma unroll
        for (int m = 16; m; m >>= 1) y += __shfl_xor_sync(0xffffffffu, y, m);
        if (h == t) d_S[w * 32 + t] = y + fob;
    }
}

// ---------------- overlap-add gather -----------------------------------------
__global__ void __launch_bounds__(256) oadd_kernel(float* __restrict__ out)
{
    int idx = blockIdx.x * blockDim.x + threadIdx.x;
    if (idx >= B_SZ * T_LEN) return;
    int b = idx / T_LEN;
    int i = idx - b * T_LEN;
    int f1 = i >> 4;
    int j  = i & 15;
    float v = 0.f;
    if (f1 < NF) v += d_S[(b * NF + f1) * 32 + j];
    if (f1 >= 1) v += d_S[(b * NF + f1 - 1) * 32 + j + 16];
    out[idx] = v;
}

// ---------------- launch -------------------------------------------------------
extern "C" void kernel_launch(void* const* d_in, const int* in_sizes, int n_in,
                              void* d_out, int out_size)
{
    const float* x    = (const float*)d_in[0];
    const float* siW  = (const float*)d_in[1];
    const float* sib  = (const float*)d_in[2];
    const float* Wih  = (const float*)d_in[3];
    const float* Whh  = (const float*)d_in[4];
    const float* bih  = (const float*)d_in[5];
    const float* bhh  = (const float*)d_in[6];
    const float* soW  = (const float*)d_in[7];
    const float* sob  = (const float*)d_in[8];
    const float* s2sW = (const float*)d_in[9];
    const float* s2sb = (const float*)d_in[10];
    const float* finW = (const float*)d_in[11];
    const float* finb = (const float*)d_in[12];
    const float* foW  = (const float*)d_in[13];
    const float* fob  = (const float*)d_in[14];
    float* out = (float*)d_out;

    cudaFuncSetAttribute(slow_kernel,
                         cudaFuncAttributeMaxDynamicSharedMemorySize, SMEM_BYTES);

    slow_kernel<<<NCTA_SLOW, 128, SMEM_BYTES>>>(
        x, siW, sib, Wih, Whh, bih, bhh, soW, sob, s2sW, s2sb);

    int fast_blocks = (BS_TOT * 32 + 255) / 256;
    fast_kernel<<<fast_blocks, 256>>>(x, finW, finb, foW, fob);

    int oadd_blocks = (B_SZ * T_LEN + 255) / 256;
    oadd_kernel<<<oadd_blocks, 256>>>(out);
}

// round 3
// speedup vs baseline: 1.2235x; 1.0365x over previous
#include <cuda_runtime.h>
#include <math.h>

// ---------------- problem constants ----------------------------------------
#define T_LEN   64000
#define B_SZ    2
#define NS      3999
#define NF      3999
#define BS_TOT  (B_SZ * NS)        // 7998
#define HFAST   32
#define ROWS    16                 // sequences per CTA
#define NCTA_SLOW ((BS_TOT + ROWS - 1) / ROWS)   // 500

// smem layout (floats):
//   seq  [32][64][16]         32768   (row-minor; slow_feat overlaid at head)
//   wTih [64][196]            12544   (u-major transposed; xw overlaid at init)
//   wThh [64][196]            12544
#define SEQ_F   (32 * 64 * 16)
#define WT_STR  196
#define WT_F    (64 * WT_STR)
#define OFF_WIH SEQ_F
#define OFF_WHH (SEQ_F + WT_F)
#define SMEM_FLOATS (SEQ_F + 2 * WT_F)
#define SMEM_BYTES  (SMEM_FLOATS * 4)            // 231424

// ---------------- device scratch --------------------------------------------
__device__ float d_A[BS_TOT * HFAST];
__device__ float d_G[BS_TOT * HFAST];
__device__ float d_S[BS_TOT * 32];

// ---------------- f32x2 helpers ---------------------------------------------
typedef unsigned long long u64;

__device__ __forceinline__ u64 pack2(float x, float y) {
    u64 r; asm("mov.b64 %0,{%1,%2};" : "=l"(r) : "f"(x), "f"(y)); return r;
}
__device__ __forceinline__ void unpack2(u64 v, float& x, float& y) {
    asm("mov.b64 {%0,%1},%2;" : "=f"(x), "=f"(y) : "l"(v));
}
__device__ __forceinline__ void ffma2(u64& d, u64 a, u64 b) {
    asm("fma.rn.f32x2 %0,%1,%2,%0;" : "+l"(d) : "l"(a), "l"(b));
}

__device__ __forceinline__ float sigmoidf_(float x) {
    return __fdividef(1.0f, 1.0f + __expf(-x));
}
__device__ __forceinline__ float tanhf_(float x) {
    float e = __expf(-2.0f * fabsf(x));
    float t = __fdividef(1.0f - e, 1.0f + e);
    return copysignf(t, x);
}
__device__ __forceinline__ float gatefn(float ar, float az, float an, float ah, float hp) {
    float r = sigmoidf_(ar);
    float z = sigmoidf_(az);
    float n = tanhf_(an + r * ah);
    return z * (hp - n) + n;
}

// ---------------- slow path --------------------------------------------------
__global__ void __launch_bounds__(256, 1) slow_kernel(
    const float* __restrict__ x,
    const float* __restrict__ siW,  const float* __restrict__ sib,
    const float* __restrict__ Wih,  const float* __restrict__ Whh,
    const float* __restrict__ bih,  const float* __restrict__ bhh,
    const float* __restrict__ soW,  const float* __restrict__ sob,
    const float* __restrict__ s2sW, const float* __restrict__ s2sb)
{
    extern __shared__ float sm[];
    float* seq  = sm;              // [t][k][row]
    float* wih  = sm + OFF_WIH;    // [u][g*64+k] transposed, stride 196
    float* whh  = sm + OFF_WHH;
    float* xw   = wih;             // overlay: x windows during init only

    const int tid = threadIdx.x;
    const int u   = tid & 63;
    const int rb  = tid >> 6;      // 0..3
    const int r0  = rb * 4;
    const int g0  = blockIdx.x * ROWS;
    const int u196 = u * WT_STR;

    // ---- x windows into xw (weight region, pre-weights): xw[r][t] -----------
    for (int i = tid; i < ROWS * 32; i += 256) {
        int r = i >> 5, t = i & 31;
        int g = g0 + r;
        float v = 0.0f;
        if (g < BS_TOT) {
            int b = g / NS;
            int s = g - b * NS;
            v = x[b * T_LEN + s * 16 + t];
        }
        xw[i] = v;
    }
    __syncthreads();

    // ---- layer-0 input: seq[t][k][r] = relu(xw*W+b) --------------------------
    for (int i = tid; i < SEQ_F; i += 256) {
        int r = i & 15;
        int k = (i >> 4) & 63;
        int t = i >> 10;
        seq[i] = fmaxf(xw[r * 32 + t] * __ldg(&siW[k]) + __ldg(&sib[k]), 0.0f);
    }

    // ---- 4 GRU layers ---------------------------------------------------------
    for (int l = 0; l < 4; ++l) {
        const float* gW = Wih + l * 12288;
        const float* gU = Whh + l * 12288;
        __syncthreads();   // prior reads of wih/whh (or xw / layer-0 writes) done
        for (int i = tid; i < 12288; i += 256) {
            int k = i / 192, j = i - k * 192;
            int g = j >> 6, uu = j & 63;
            wih[uu * WT_STR + g * 64 + k] = gW[i];
            whh[uu * WT_STR + g * 64 + k] = gU[i];
        }
        const float b_r  = __ldg(&bih[l*192 + u])       + __ldg(&bhh[l*192 + u]);
        const float b_z  = __ldg(&bih[l*192 + 64 + u])  + __ldg(&bhh[l*192 + 64 + u]);
        const float b_xn = __ldg(&bih[l*192 + 128 + u]);
        const float b_hn = __ldg(&bhh[l*192 + 128 + u]);
        const u64 b2r = pack2(b_r,  b_r);
        const u64 b2z = pack2(b_z,  b_z);
        const u64 b2n = pack2(b_xn, b_xn);
        const u64 b2h = pack2(b_hn, b_hn);
        __syncthreads();

        float hp[4] = {0.f, 0.f, 0.f, 0.f};

        for (int t = 0; t < 32; ++t) {
            u64 ar[2] = {b2r, b2r};
            u64 az[2] = {b2z, b2z};
            u64 an[2] = {b2n, b2n};
            u64 ah[2] = {b2h, b2h};

            // ---- Wih GEMM: reads seq[t] (relu'd prev-layer output) ----------
            {
                const float* st = seq + t * 1024 + r0;
                #pragma unroll 4
                for (int k0 = 0; k0 < 64; k0 += 4) {
                    float4 wr = *(const float4*)(wih + u196 + k0);
                    float4 wz = *(const float4*)(wih + u196 + 64 + k0);
                    float4 wn = *(const float4*)(wih + u196 + 128 + k0);
                    const float* wrp = &wr.x;
                    const float* wzp = &wz.x;
                    const float* wnp = &wn.x;
                    #pragma unroll
                    for (int j = 0; j < 4; ++j) {
                        ulonglong2 s = *(const ulonglong2*)(st + (k0 + j) * 16);
                        u64 w2;
                        w2 = pack2(wrp[j], wrp[j]);
                        ffma2(ar[0], s.x, w2); ffma2(ar[1], s.y, w2);
                        w2 = pack2(wzp[j], wzp[j]);
                        ffma2(az[0], s.x, w2); ffma2(az[1], s.y, w2);
                        w2 = pack2(wnp[j], wnp[j]);
                        ffma2(an[0], s.x, w2); ffma2(an[1], s.y, w2);
                    }
                }
            }
            // ---- Whh GEMM: reads seq[t-1] (pre-relu h_{t-1}) -----------------
            if (t > 0) {
                const float* sp = seq + (t - 1) * 1024 + r0;
                #pragma unroll 4
                for (int k0 = 0; k0 < 64; k0 += 4) {
                    float4 wr = *(const float4*)(whh + u196 + k0);
                    float4 wz = *(const float4*)(whh + u196 + 64 + k0);
                    float4 wn = *(const float4*)(whh + u196 + 128 + k0);
                    const float* wrp = &wr.x;
                    const float* wzp = &wz.x;
                    const float* wnp = &wn.x;
                    #pragma unroll
                    for (int j = 0; j < 4; ++j) {
                        ulonglong2 s = *(const ulonglong2*)(sp + (k0 + j) * 16);
                        u64 w2;
                        w2 = pack2(wrp[j], wrp[j]);
                        ffma2(ar[0], s.x, w2); ffma2(ar[1], s.y, w2);
                        w2 = pack2(wzp[j], wzp[j]);
                        ffma2(az[0], s.x, w2); ffma2(az[1], s.y, w2);
                        w2 = pack2(wnp[j], wnp[j]);
                        ffma2(ah[0], s.x, w2); ffma2(ah[1], s.y, w2);
                    }
                }
            }
            __syncthreads();   // all reads of seq[t], seq[t-1] complete

            float hn[4];
            float zr[4], zz[4], zn[4], zh[4];
            unpack2(ar[0], zr[0], zr[1]); unpack2(ar[1], zr[2], zr[3]);
            unpack2(az[0], zz[0], zz[1]); unpack2(az[1], zz[2], zz[3]);
            unpack2(an[0], zn[0], zn[1]); unpack2(an[1], zn[2], zn[3]);
            unpack2(ah[0], zh[0], zh[1]); unpack2(ah[1], zh[2], zh[3]);
            #pragma unroll
            for (int i = 0; i < 4; ++i)
                hn[i] = gatefn(zr[i], zz[i], zn[i], zh[i], hp[i]);

            // write pre-relu h_t -> seq[t]; relu(h_{t-1}) -> seq[t-1]
            *(float4*)(seq + t * 1024 + u * 16 + r0) =
                make_float4(hn[0], hn[1], hn[2], hn[3]);
            if (t > 0) {
                *(float4*)(seq + (t - 1) * 1024 + u * 16 + r0) =
                    make_float4(fmaxf(hp[0], 0.f), fmaxf(hp[1], 0.f),
                                fmaxf(hp[2], 0.f), fmaxf(hp[3], 0.f));
            }
            #pragma unroll
            for (int i = 0; i < 4; ++i) hp[i] = hn[i];
            __syncthreads();   // writes visible before next step
        }
        // finalize: relu(h_31) -> seq[31]
        *(float4*)(seq + 31 * 1024 + u * 16 + r0) =
            make_float4(fmaxf(hp[0], 0.f), fmaxf(hp[1], 0.f),
                        fmaxf(hp[2], 0.f), fmaxf(hp[3], 0.f));
    }
    __syncthreads();

    // ---- head: slow_feat = seq[31] @ soW + sob ; eps = sf @ s2sW + s2sb ------
    for (int i = tid; i < 64 * 64; i += 256) {
        wih[i] = soW[i];
        whh[i] = s2sW[i];
    }
    __syncthreads();

    {
        float acc[4];
        float bb = __ldg(&sob[u]);
        #pragma unroll
        for (int i = 0; i < 4; ++i) acc[i] = bb;
        const float* sl = seq + 31 * 1024 + r0;   // already relu'd
        #pragma unroll 8
        for (int k = 0; k < 64; ++k) {
            float4 v = *(const float4*)(sl + k * 16);
            float w = wih[k * 64 + u];
            acc[0] += v.x * w; acc[1] += v.y * w;
            acc[2] += v.z * w; acc[3] += v.w * w;
        }
        // slow_feat -> seq[0] region as [c=u][row]
        *(float4*)(seq + u * 16 + r0) = make_float4(acc[0], acc[1], acc[2], acc[3]);
    }
    __syncthreads();

    {
        float acc[4];
        float bb = __ldg(&s2sb[u]);
        #pragma unroll
        for (int i = 0; i < 4; ++i) acc[i] = bb;
        #pragma unroll 8
        for (int k = 0; k < 64; ++k) {
            float4 v = *(const float4*)(seq + k * 16 + r0);
            float w = whh[k * 64 + u];
            acc[0] += v.x * w; acc[1] += v.y * w;
            acc[2] += v.z * w; acc[3] += v.w * w;
        }
        #pragma unroll
        for (int i = 0; i < 4; ++i) {
            int g = g0 + r0 + i;
            if (g < BS_TOT) {
                if (u < HFAST) d_A[g * HFAST + u] = sigmoidf_(acc[i]);
                else           d_G[g * HFAST + (u - HFAST)] = acc[i];
            }
        }
    }
}

// ---------------- fast path: diagonal SSM, warp per frame -------------------
__global__ void __launch_bounds__(256) fast_kernel(
    const float* __restrict__ x,
    const float* __restrict__ finW, const float* __restrict__ finb,
    const float* __restrict__ foutW, const float* __restrict__ foutb)
{
    int w = (blockIdx.x * blockDim.x + threadIdx.x) >> 5;
    int h = threadIdx.x & 31;
    if (w >= BS_TOT) return;
    int b = w / NF;
    int f = w - b * NF;

    float A  = d_A[w * HFAST + h];
    float G  = d_G[w * HFAST + h];
    float fw = __ldg(&finW[h]);
    float fb = __ldg(&finb[h]);
    float fo = __ldg(&foutW[h]);
    float fob = __ldg(&foutb[0]);

    const float* xp = x + b * T_LEN + f * 16;
    float hs = 0.f;
    #pragma unroll
    for (int t = 0; t < 32; ++t) {
        float e = (xp[t] * fw + fb) * G;
        hs = A * hs + e;
        float y = hs * fo;
        #pragma unroll
        for (int m = 16; m; m >>= 1) y += __shfl_xor_sync(0xffffffffu, y, m);
        if (h == t) d_S[w * 32 + t] = y + fob;
    }
}

// ---------------- overlap-add gather -----------------------------------------
__global__ void __launch_bounds__(256) oadd_kernel(float* __restrict__ out)
{
    int idx = blockIdx.x * blockDim.x + threadIdx.x;
    if (idx >= B_SZ * T_LEN) return;
    int b = idx / T_LEN;
    int i = idx - b * T_LEN;
    int f1 = i >> 4;
    int j  = i & 15;
    float v = 0.f;
    if (f1 < NF) v += d_S[(b * NF + f1) * 32 + j];
    if (f1 >= 1) v += d_S[(b * NF + f1 - 1) * 32 + j + 16];
    out[idx] = v;
}

// ---------------- launch -------------------------------------------------------
extern "C" void kernel_launch(void* const* d_in, const int* in_sizes, int n_in,
                              void* d_out, int out_size)
{
    const float* x    = (const float*)d_in[0];
    const float* siW  = (const float*)d_in[1];
    const float* sib  = (const float*)d_in[2];
    const float* Wih  = (const float*)d_in[3];
    const float* Whh  = (const float*)d_in[4];
    const float* bih  = (const float*)d_in[5];
    const float* bhh  = (const float*)d_in[6];
    const float* soW  = (const float*)d_in[7];
    const float* sob  = (const float*)d_in[8];
    const float* s2sW = (const float*)d_in[9];
    const float* s2sb = (const float*)d_in[10];
    const float* finW = (const float*)d_in[11];
    const float* finb = (const float*)d_in[12];
    const float* foW  = (const float*)d_in[13];
    const float* fob  = (const float*)d_in[14];
    float* out = (float*)d_out;

    cudaFuncSetAttribute(slow_kernel,
                         cudaFuncAttributeMaxDynamicSharedMemorySize, SMEM_BYTES);

    slow_kernel<<<NCTA_SLOW, 256, SMEM_BYTES>>>(
        x, siW, sib, Wih, Whh, bih, bhh, soW, sob, s2sW, s2sb);

    int fast_blocks = (BS_TOT * 32 + 255) / 256;
    fast_kernel<<<fast_blocks, 256>>>(x, finW, finb, foW, fob);

    int oadd_blocks = (B_SZ * T_LEN + 255) / 256;
    oadd_kernel<<<oadd_blocks, 256>>>(out);
}